// round 9
// baseline (speedup 1.0000x reference)
#include <cuda_runtime.h>
#include <cfloat>
#include <math.h>

// Fixed problem shape (setup_inputs): N=8192, IN_F=512, OUT_F=64, C=2, k=32
#define N_     8192
#define INF_   512
#define OUTF_  64
#define C_     2
#define RMAX   16384
#define CAP2   320
#define WCAP   40      // CAP2 / 8 warps
#define KMAX   64
#define T0     2.2f

// Static device scratch (no allocations allowed)
__device__ float  g_h[N_ * OUTF_];              // 2MB   h = x @ W^T
__device__ float2 g_cand[(long)RMAX * CAP2];    // 40MB  per-warp slot ranges
__device__ int    g_cnt8[RMAX * 8];             // per-warp candidate counts

// ---------------------------------------------------------------------------
// Kernel 1: h = x @ W^T. Block = 32 rows x 64 f, 256 threads, 2x4 tile.
// float2 LDS (stride-66 pad, 8B aligned -> conflict-free), grid = 256.
// ---------------------------------------------------------------------------
__global__ void __launch_bounds__(256) h_kernel(const float* __restrict__ x,
                                                const float* __restrict__ W) {
    __shared__ float x_s[32 * 64];   // [row][kk]     8KB
    __shared__ float w_s[64 * 66];   // [f][kk] pad  16.9KB
    const int t  = threadIdx.x;
    const int tx = t & 15;           // f lane: f = tx + 16*i
    const int ty = t >> 4;           // rows ty*2, ty*2+1
    const int rowBase = blockIdx.x * 32;

    const float4* x4 = (const float4*)x;   // row = 128 float4
    const float4* W4 = (const float4*)W;

    float acc[2][4];
#pragma unroll
    for (int j = 0; j < 2; j++)
#pragma unroll
        for (int i = 0; i < 4; i++) acc[j][i] = 0.f;

    for (int ch = 0; ch < 8; ch++) {   // 64-kk chunks
#pragma unroll
        for (int i = 0; i < 2; i++) {  // x: 512 float4
            int idx = t + 256 * i;
            int rr = idx >> 4, c4 = idx & 15;
            float4 a = x4[(long)(rowBase + rr) * 128 + ch * 16 + c4];
            *(float4*)&x_s[rr * 64 + c4 * 4] = a;
        }
#pragma unroll
        for (int i = 0; i < 4; i++) {  // W: 1024 float4
            int idx = t + 256 * i;
            int ff = idx >> 4, c4 = idx & 15;
            float4 b = W4[(long)ff * 128 + ch * 16 + c4];
            float* d = &w_s[ff * 66 + c4 * 4];
            *(float2*)(d)     = make_float2(b.x, b.y);
            *(float2*)(d + 2) = make_float2(b.z, b.w);
        }
        __syncthreads();

#pragma unroll 8
        for (int kk = 0; kk < 64; kk += 2) {
            float2 xv[2], wv[4];
#pragma unroll
            for (int j = 0; j < 2; j++)
                xv[j] = *(const float2*)&x_s[(ty * 2 + j) * 64 + kk];
#pragma unroll
            for (int i = 0; i < 4; i++)
                wv[i] = *(const float2*)&w_s[(tx + 16 * i) * 66 + kk];
#pragma unroll
            for (int j = 0; j < 2; j++)
#pragma unroll
                for (int i = 0; i < 4; i++) {
                    acc[j][i] = fmaf(xv[j].x, wv[i].x, acc[j][i]);
                    acc[j][i] = fmaf(xv[j].y, wv[i].y, acc[j][i]);
                }
        }
        __syncthreads();
    }
#pragma unroll
    for (int j = 0; j < 2; j++)
#pragma unroll
        for (int i = 0; i < 4; i++)
            g_h[(long)(rowBase + ty * 2 + j) * OUTF_ + tx + 16 * i] = acc[j][i];
}

// ---------------------------------------------------------------------------
// Kernel 2 (stream): read row once, zero att, extract candidates >= T0.
// Per-warp private slot range + register counter via ballot/popc:
// NO atomics, NO shared memory, NO block sync.
// ---------------------------------------------------------------------------
__global__ void __launch_bounds__(256) stream_kernel(const float* __restrict__ araw,
                                                     float* __restrict__ att) {
    const int t    = threadIdx.x;
    const int lane = t & 31;
    const int wid  = t >> 5;
    const long r   = blockIdx.x;

    const float4* src = (const float4*)(araw + r * (long)N_);
    float4* dst = att ? (float4*)(att + r * (long)N_) : nullptr;
    float2* cb = g_cand + r * CAP2 + wid * WCAP;
    const float4 z = make_float4(0.f, 0.f, 0.f, 0.f);
    const unsigned below = (1u << lane) - 1u;
    int cnt = 0;   // warp-uniform (ballot-derived)

#define EX(val, gi) do {                                                       \
        unsigned m_ = __ballot_sync(0xffffffffu, (val) >= T0);                 \
        if ((val) >= T0) {                                                     \
            int p_ = cnt + __popc(m_ & below);                                 \
            if (p_ < WCAP) cb[p_] = make_float2((val), __int_as_float(gi));    \
        }                                                                      \
        cnt += __popc(m_);                                                     \
    } while (0)

#pragma unroll
    for (int i = 0; i < 8; i++) {
        int e4 = wid * 256 + i * 32 + lane;   // warp-contiguous segment
        float4 v = __ldcs(src + e4);
        if (dst) __stcs(dst + e4, z);
        int b4 = 4 * e4;
        EX(v.x, b4);
        EX(v.y, b4 + 1);
        EX(v.z, b4 + 2);
        EX(v.w, b4 + 3);
    }
#undef EX
    if (lane == 0) g_cnt8[r * 8 + wid] = cnt;
}

// ---------------------------------------------------------------------------
// Kernel 3 (rank): merge per-warp candidate lists, exact top-k (jax
// tie-break), softmax, scatter att values, gather h' into output.
// ---------------------------------------------------------------------------
__global__ void __launch_bounds__(128) rank_kernel(const float* __restrict__ araw,
                                                   const int*   __restrict__ kptr,
                                                   float*       __restrict__ out,
                                                   float*       __restrict__ att) {
    __shared__ float cval[CAP2];
    __shared__ int   cidx[CAP2];
    __shared__ int   sidx[KMAX];
    __shared__ float sw[KMAX];
    __shared__ float s_red[4];
    __shared__ float s_bv[4];
    __shared__ int   s_bi[4];
    __shared__ float s_M;
    __shared__ float s_inv;
    __shared__ float s_lastV;
    __shared__ int   s_lastI;

    const int t    = threadIdx.x;
    const int lane = t & 31;
    const int wid  = t >> 5;
    const long r   = blockIdx.x;

    int k = 32;
    if (kptr) { k = *kptr; if (k < 1) k = 1; if (k > KMAX) k = KMAX; }

    if (t < KMAX) sw[t] = 0.f;   // zero-pad for fixed-tree sum

    // merge per-warp counts (broadcast loads; all threads read 8 ints)
    int cnts[8], offs[8], m = 0;
    bool ok = true;
#pragma unroll
    for (int j = 0; j < 8; j++) {
        cnts[j] = g_cnt8[r * 8 + j];
        offs[j] = m;
        m += cnts[j];
        ok = ok && (cnts[j] <= WCAP);
    }
    ok = ok && (m >= k);

    if (ok) {
        const float2* cbase = g_cand + r * CAP2;
#pragma unroll
        for (int j = 0; j < 8; j++)
            for (int i = t; i < cnts[j]; i += 128) {
                float2 c = cbase[j * WCAP + i];
                cval[offs[j] + i] = c.x;
                cidx[offs[j] + i] = __float_as_int(c.y);
            }
        __syncthreads();

        // max over candidates (row max is among them since m >= k >= 1)
        float lm = -FLT_MAX;
        for (int i = t; i < m; i += 128) lm = fmaxf(lm, cval[i]);
#pragma unroll
        for (int o = 16; o > 0; o >>= 1)
            lm = fmaxf(lm, __shfl_xor_sync(0xffffffffu, lm, o));
        if (lane == 0) s_red[wid] = lm;
        __syncthreads();
        if (t == 0)
            s_M = fmaxf(fmaxf(s_red[0], s_red[1]), fmaxf(s_red[2], s_red[3]));
        __syncthreads();
        const float M = s_M;

        // exact rank: value desc, index asc
        for (int i = t; i < m; i += 128) {
            float vi = cval[i];
            int   ii = cidx[i];
            int rank = 0;
            for (int j = 0; j < m; j++) {
                float vj = cval[j];
                rank += (vj > vi) || (vj == vi && cidx[j] < ii);
            }
            if (rank < k) { sidx[rank] = ii; sw[rank] = expf(vi - M); }
        }
        __syncthreads();
    } else {
        // robust fallback: k deterministic arg-max passes over the global row
        if (t == 0) { s_lastV = FLT_MAX; s_lastI = -1; }
        __syncthreads();
        const float* rowg = araw + r * (long)N_;
        for (int p = 0; p < k; p++) {
            float lastV = s_lastV; int lastI = s_lastI;
            float bv = -FLT_MAX; int bi = N_;
            for (int e = t; e < N_; e += 128) {
                float vv = rowg[e];
                bool after = (vv < lastV) || (vv == lastV && e > lastI);
                if (after && ((vv > bv) || (vv == bv && e < bi))) { bv = vv; bi = e; }
            }
#pragma unroll
            for (int o = 16; o > 0; o >>= 1) {
                float ov = __shfl_xor_sync(0xffffffffu, bv, o);
                int   oi = __shfl_xor_sync(0xffffffffu, bi, o);
                if ((ov > bv) || (ov == bv && oi < bi)) { bv = ov; bi = oi; }
            }
            if (lane == 0) { s_bv[wid] = bv; s_bi[wid] = bi; }
            __syncthreads();
            if (t == 0) {
                float gv = s_bv[0]; int gi = s_bi[0];
#pragma unroll
                for (int j = 1; j < 4; j++) {
                    if ((s_bv[j] > gv) || (s_bv[j] == gv && s_bi[j] < gi)) { gv = s_bv[j]; gi = s_bi[j]; }
                }
                if (p == 0) s_M = gv;
                sidx[p] = gi; sw[p] = expf(gv - s_M);
                s_lastV = gv; s_lastI = gi;
            }
            __syncthreads();
        }
    }

    // deterministic softmax denominator: fixed warp-0 shuffle tree
    if (wid == 0) {
        float s = sw[lane] + sw[lane + 32];
#pragma unroll
        for (int o = 16; o > 0; o >>= 1)
            s += __shfl_xor_sync(0xffffffffu, s, o);
        if (lane == 0) s_inv = 1.0f / s;
    }
    __syncthreads();
    const float inv = s_inv;

    // scatter k softmax values (zeros already written by stream_kernel)
    if (att && t < k) att[r * (long)N_ + sidx[t]] = sw[t] * inv;

    // h_prime row -> concat-transposed output [n, c*OUTF + f]
    if (out && t < OUTF_) {
        float acc = 0.f;
        for (int p = 0; p < k; p++)
            acc = fmaf(sw[p] * inv, g_h[(long)sidx[p] * OUTF_ + t], acc);
        const int c = (int)(r / N_);
        const int n = (int)(r % N_);
        out[(long)n * (C_ * OUTF_) + c * OUTF_ + t] = acc;
    }
}

// ---------------------------------------------------------------------------
extern "C" void kernel_launch(void* const* d_in, const int* in_sizes, int n_in,
                              void* d_out, int out_size) {
    const float* x    = (const float*)d_in[0];
    const float* W    = (const float*)d_in[1];
    const float* araw = (const float*)d_in[2];
    const int*   kptr = (n_in > 3) ? (const int*)d_in[3] : nullptr;

    const long attElems = (long)in_sizes[2];        // R * N
    const int  R        = (int)(attElems / N_);     // 16384
    const long outElems = (long)N_ * C_ * OUTF_;    // 1,048,576

    float* outp = nullptr;
    float* attp = nullptr;
    const long osz = (long)out_size;
    if (osz >= outElems + attElems) {
        outp = (float*)d_out;
        attp = (float*)d_out + outElems;   // tuple order: (out, att)
    } else if (osz == attElems) {
        attp = (float*)d_out;
    } else {
        outp = (float*)d_out;
    }

    if (outp) h_kernel<<<N_ / 32, 256>>>(x, W);
    stream_kernel<<<R, 256>>>(araw, attp);
    rank_kernel<<<R, 128>>>(araw, kptr, outp, attp);
}

// round 10
// speedup vs baseline: 1.7126x; 1.7126x over previous
#include <cuda_runtime.h>
#include <cfloat>
#include <math.h>

// Fixed problem shape (setup_inputs): N=8192, IN_F=512, OUT_F=64, C=2, k=32
#define N_     8192
#define INF_   512
#define OUTF_  64
#define C_     2
#define WCAP   64      // per-warp candidate capacity (13 sigma)
#define CAP    512     // 8 * WCAP
#define KMAX   64
#define T0     2.2f

// Scratch for h = x @ W^T  [N_, OUTF_]  (2MB, device global: no allocations)
__device__ float g_h[N_ * OUTF_];

// ---------------------------------------------------------------------------
// Kernel 1: h = x @ W^T. Tiled GEMM: block = 64 rows x 64 f, 256 threads,
// thread tile 4x4. W smem stride 65 (pad) + f = tx+16*i => conflict-free LDS.
// (Proven R8 version: 33us.)
// ---------------------------------------------------------------------------
__global__ void __launch_bounds__(256) h_kernel(const float* __restrict__ x,
                                                const float* __restrict__ W) {
    __shared__ float x_s[64 * 64];   // [row][kk]   16KB
    __shared__ float w_s[64 * 65];   // [f][kk] pad 16.25KB
    const int t  = threadIdx.x;
    const int tx = t & 15;           // f lane: f = tx + 16*i
    const int ty = t >> 4;           // rows ty*4 .. ty*4+3
    const int rowBase = blockIdx.x * 64;

    const float4* x4 = (const float4*)x;   // row = 128 float4
    const float4* W4 = (const float4*)W;

    float acc[4][4];
#pragma unroll
    for (int j = 0; j < 4; j++)
#pragma unroll
        for (int i = 0; i < 4; i++) acc[j][i] = 0.f;

    for (int ch = 0; ch < 8; ch++) {   // 64-kk chunks
#pragma unroll
        for (int i = 0; i < 4; i++) {
            int idx = t + 256 * i;         // 0..1023
            int rr = idx >> 4, c4 = idx & 15;
            float4 a = x4[(long)(rowBase + rr) * 128 + ch * 16 + c4];
            *(float4*)&x_s[rr * 64 + c4 * 4] = a;
            float4 b = W4[(long)rr * 128 + ch * 16 + c4];  // rr = f here
            float* d = &w_s[rr * 65 + c4 * 4];
            d[0] = b.x; d[1] = b.y; d[2] = b.z; d[3] = b.w;
        }
        __syncthreads();

#pragma unroll 4
        for (int kk = 0; kk < 64; kk++) {
            float xv[4], wv[4];
#pragma unroll
            for (int j = 0; j < 4; j++) xv[j] = x_s[(ty * 4 + j) * 64 + kk];
#pragma unroll
            for (int i = 0; i < 4; i++) wv[i] = w_s[(tx + 16 * i) * 65 + kk];
#pragma unroll
            for (int j = 0; j < 4; j++)
#pragma unroll
                for (int i = 0; i < 4; i++)
                    acc[j][i] = fmaf(xv[j], wv[i], acc[j][i]);
        }
        __syncthreads();
    }
#pragma unroll
    for (int j = 0; j < 4; j++)
#pragma unroll
        for (int i = 0; i < 4; i++)
            g_h[(long)(rowBase + ty * 4 + j) * OUTF_ + tx + 16 * i] = acc[j][i];
}

// ---------------------------------------------------------------------------
// Kernel 2 (fused): per attention row (16384 blocks, 256 threads).
// Stream: 4-batched ldcs (MLP=4) + interleaved zero stcs; extraction via
// per-warp smem atomic counters (no cross-warp contention, no ballot chain).
// Then: exact rank (jax tie-break), softmax, scatter att, gather h'.
// ---------------------------------------------------------------------------
__global__ void __launch_bounds__(256) topk_kernel(const float* __restrict__ araw,
                                                   const int*   __restrict__ kptr,
                                                   float*       __restrict__ out,
                                                   float*       __restrict__ att) {
    __shared__ float cvw[8][WCAP];
    __shared__ int   ciw[8][WCAP];
    __shared__ int   s_cw[8];
    __shared__ float cval[CAP];
    __shared__ int   cidx[CAP];
    __shared__ int   sidx[KMAX];
    __shared__ float sw[KMAX];
    __shared__ float s_red[8];
    __shared__ float s_bv[8];
    __shared__ int   s_bi[8];
    __shared__ float s_M;
    __shared__ float s_inv;
    __shared__ float s_lastV;
    __shared__ int   s_lastI;

    const int t    = threadIdx.x;
    const int lane = t & 31;
    const int wid  = t >> 5;
    const long r   = blockIdx.x;

    int k = 32;
    if (kptr) { k = *kptr; if (k < 1) k = 1; if (k > KMAX) k = KMAX; }

    if (t < 8)    s_cw[t] = 0;
    if (t < KMAX) sw[t]   = 0.f;   // zero-pad for fixed-tree sum
    __syncthreads();

    // ---- stream: 4-batched loads (MLP=4), interleaved zero stores ----
    const float4* src = (const float4*)(araw + r * (long)N_);
    float4* dst = att ? (float4*)(att + r * (long)N_) : nullptr;
    const float4 z = make_float4(0.f, 0.f, 0.f, 0.f);

#define EXT(val, gi) do {                                                      \
        if ((val) >= T0) {                                                     \
            int p_ = atomicAdd(&s_cw[wid], 1);                                 \
            if (p_ < WCAP) { cvw[wid][p_] = (val); ciw[wid][p_] = (gi); }      \
        }                                                                      \
    } while (0)

#pragma unroll
    for (int g = 0; g < 2; g++) {
        float4 v[4];
#pragma unroll
        for (int i = 0; i < 4; i++)
            v[i] = __ldcs(src + t + 256 * (g * 4 + i));     // 4 in flight
        if (dst) {
#pragma unroll
            for (int i = 0; i < 4; i++)
                __stcs(dst + t + 256 * (g * 4 + i), z);
        }
#pragma unroll
        for (int i = 0; i < 4; i++) {
            int b4 = 4 * (t + 256 * (g * 4 + i));
            EXT(v[i].x, b4);
            EXT(v[i].y, b4 + 1);
            EXT(v[i].z, b4 + 2);
            EXT(v[i].w, b4 + 3);
        }
    }
#undef EXT
    __syncthreads();

    // ---- merge per-warp counts ----
    int cnts[8], offs[8], m = 0;
    bool ok = true;
#pragma unroll
    for (int j = 0; j < 8; j++) {
        cnts[j] = s_cw[j];
        offs[j] = m;
        m += cnts[j];
        ok = ok && (cnts[j] <= WCAP);
    }
    ok = ok && (m >= k);

    if (ok) {
        // compact per-warp lists into contiguous cval/cidx
#pragma unroll
        for (int j = 0; j < 8; j++)
            for (int i = t; i < cnts[j]; i += 256) {
                cval[offs[j] + i] = cvw[j][i];
                cidx[offs[j] + i] = ciw[j][i];
            }
        __syncthreads();

        // max over candidates (row max is among them since m >= k >= 1)
        float lm = -FLT_MAX;
        for (int i = t; i < m; i += 256) lm = fmaxf(lm, cval[i]);
#pragma unroll
        for (int o = 16; o > 0; o >>= 1)
            lm = fmaxf(lm, __shfl_xor_sync(0xffffffffu, lm, o));
        if (lane == 0) s_red[wid] = lm;
        __syncthreads();
        if (t == 0) {
            float mm = s_red[0];
#pragma unroll
            for (int j = 1; j < 8; j++) mm = fmaxf(mm, s_red[j]);
            s_M = mm;
        }
        __syncthreads();
        const float M = s_M;

        // exact rank: value desc, index asc (jax tie-break)
        for (int i = t; i < m; i += 256) {
            float vi = cval[i];
            int   ii = cidx[i];
            int rank = 0;
            for (int j = 0; j < m; j++) {
                float vj = cval[j];
                rank += (vj > vi) || (vj == vi && cidx[j] < ii);
            }
            if (rank < k) { sidx[rank] = ii; sw[rank] = expf(vi - M); }
        }
        __syncthreads();
    } else {
        // robust fallback: k deterministic arg-max passes over the global row
        if (t == 0) { s_lastV = FLT_MAX; s_lastI = -1; }
        __syncthreads();
        const float* rowg = araw + r * (long)N_;
        for (int p = 0; p < k; p++) {
            float lastV = s_lastV; int lastI = s_lastI;
            float bv = -FLT_MAX; int bi = N_;
            for (int e = t; e < N_; e += 256) {
                float vv = rowg[e];
                bool after = (vv < lastV) || (vv == lastV && e > lastI);
                if (after && ((vv > bv) || (vv == bv && e < bi))) { bv = vv; bi = e; }
            }
#pragma unroll
            for (int o = 16; o > 0; o >>= 1) {
                float ov = __shfl_xor_sync(0xffffffffu, bv, o);
                int   oi = __shfl_xor_sync(0xffffffffu, bi, o);
                if ((ov > bv) || (ov == bv && oi < bi)) { bv = ov; bi = oi; }
            }
            if (lane == 0) { s_bv[wid] = bv; s_bi[wid] = bi; }
            __syncthreads();
            if (t == 0) {
                float gv = s_bv[0]; int gi = s_bi[0];
#pragma unroll
                for (int j = 1; j < 8; j++) {
                    if ((s_bv[j] > gv) || (s_bv[j] == gv && s_bi[j] < gi)) { gv = s_bv[j]; gi = s_bi[j]; }
                }
                if (p == 0) s_M = gv;
                sidx[p] = gi; sw[p] = expf(gv - s_M);
                s_lastV = gv; s_lastI = gi;
            }
            __syncthreads();
        }
    }

    // ---- deterministic softmax denominator: fixed warp-0 shuffle tree ----
    if (wid == 0) {
        float s = sw[lane] + sw[lane + 32];
#pragma unroll
        for (int o = 16; o > 0; o >>= 1)
            s += __shfl_xor_sync(0xffffffffu, s, o);
        if (lane == 0) s_inv = 1.0f / s;
    }
    __syncthreads();
    const float inv = s_inv;

    // ---- scatter the k softmax values (zeros already streamed out) ----
    if (att && t < k) att[r * (long)N_ + sidx[t]] = sw[t] * inv;

    // ---- h_prime row -> concat-transposed output [n, c*OUTF + f] ----
    if (out && t < OUTF_) {
        float acc = 0.f;
        for (int p = 0; p < k; p++)
            acc = fmaf(sw[p] * inv, g_h[(long)sidx[p] * OUTF_ + t], acc);
        const int c = (int)(r / N_);
        const int n = (int)(r % N_);
        out[(long)n * (C_ * OUTF_) + c * OUTF_ + t] = acc;
    }
}

// ---------------------------------------------------------------------------
extern "C" void kernel_launch(void* const* d_in, const int* in_sizes, int n_in,
                              void* d_out, int out_size) {
    const float* x    = (const float*)d_in[0];
    const float* W    = (const float*)d_in[1];
    const float* araw = (const float*)d_in[2];
    const int*   kptr = (n_in > 3) ? (const int*)d_in[3] : nullptr;

    const long attElems = (long)in_sizes[2];        // R * N
    const int  R        = (int)(attElems / N_);     // 16384
    const long outElems = (long)N_ * C_ * OUTF_;    // 1,048,576

    float* outp = nullptr;
    float* attp = nullptr;
    const long osz = (long)out_size;
    if (osz >= outElems + attElems) {
        outp = (float*)d_out;
        attp = (float*)d_out + outElems;   // tuple order: (out, att)
    } else if (osz == attElems) {
        attp = (float*)d_out;
    } else {
        outp = (float*)d_out;
    }

    if (outp) h_kernel<<<N_ / 64, 256>>>(x, W);
    topk_kernel<<<R, 256>>>(araw, kptr, outp, attp);
}